// round 1
// baseline (speedup 1.0000x reference)
#include <cuda_runtime.h>

// Problem constants (fixed by setup_inputs)
#define B_ 16
#define T_ 8192
#define D_ 64
#define CHUNK 16          // == WINDOW
#define CPT 8             // chunks per thread -> 128 timesteps per thread
#define TPT (CHUNK * CPT) // 128
#define YDIM 4
#define BLOCK_T (TPT * YDIM) // 512 timesteps per block

__device__ __forceinline__ float fexp2(float x) {
    float y; asm("ex2.approx.ftz.f32 %0, %1;" : "=f"(y) : "f"(x)); return y;
}
__device__ __forceinline__ float flog2(float x) {
    float y; asm("lg2.approx.ftz.f32 %0, %1;" : "=f"(y) : "f"(x)); return y;
}

// out[b,t,d] = -(1/5) * log( sum_{k=0..15} exp(-5 * x[b, max(t-k,0), d]) )
// Chunked prefix/suffix decomposition: window [t-15, t] spans at most two
// 16-aligned chunks; window_sum = prefix_cur[r] + suffix_prev[r+1].
__global__ __launch_bounds__(256) void always_kernel(
    const float* __restrict__ lower,
    const float* __restrict__ upper,
    float* __restrict__ out)
{
    const float C1 = -7.2134752044448169f;   // -5 * log2(e)
    const float C2 = -0.13862943611198906f;  // -ln(2) / 5

    const int d  = threadIdx.x;              // 0..63 (lanes -> consecutive d: coalesced)
    const int b  = blockIdx.y;               // 0..15
    const int tr = blockIdx.z;               // 0: lower, 1: upper
    const int t0 = blockIdx.x * BLOCK_T + threadIdx.y * TPT;

    const float* src = tr ? upper : lower;
    float*       dst = out + (size_t)tr * ((size_t)B_ * T_ * D_);

    const float* col  = src + (size_t)b * T_ * D_ + d;   // index by t*D_
    float*       ocol = dst + (size_t)b * T_ * D_ + d;

    // Build the initial suffix sums from the 15 preceding (index-clamped) values.
    // suf[k] = sum_{j=k..15} exp(-5 * x[t0-16+j])   (k = 1..15)
    // The clamp to index 0 reproduces h0's replication of x[:,0,:] exactly
    // (duplicates ARE counted in the logsumexp, matching the reference).
    float suf[16];
    {
        float ep[16];
        #pragma unroll
        for (int k = 1; k < 16; k++) {
            int t = t0 - 16 + k;
            if (t < 0) t = 0;
            ep[k] = fexp2(col[t * D_] * C1);
        }
        float run = 0.0f;
        #pragma unroll
        for (int k = 15; k >= 1; k--) { run += ep[k]; suf[k] = run; }
    }

    int tc = t0;
    #pragma unroll 1
    for (int c = 0; c < CPT; c++) {
        // 16 independent loads -> high MLP; one coalesced 128B txn per warp each.
        float e[16];
        #pragma unroll
        for (int r = 0; r < 16; r++)
            e[r] = fexp2(col[(tc + r) * D_] * C1);

        // Running prefix + previous-chunk suffix = exact 16-term window sum.
        float pre = 0.0f;
        #pragma unroll
        for (int r = 0; r < 16; r++) {
            pre += e[r];
            float s = (r < 15) ? (pre + suf[r + 1]) : pre;
            ocol[(tc + r) * D_] = flog2(s) * C2;
        }

        // This chunk becomes the "previous chunk" for the next iteration.
        float run = 0.0f;
        #pragma unroll
        for (int k = 15; k >= 1; k--) { run += e[k]; suf[k] = run; }

        tc += CHUNK;
    }
}

extern "C" void kernel_launch(void* const* d_in, const int* in_sizes, int n_in,
                              void* d_out, int out_size) {
    const float* lower = (const float*)d_in[0];
    const float* upper = (const float*)d_in[1];
    float* out = (float*)d_out;

    dim3 block(D_, YDIM);                 // 64 x 4 = 256 threads
    dim3 grid(T_ / BLOCK_T, B_, 2);       // 16 x 16 x 2 = 512 blocks
    always_kernel<<<grid, block>>>(lower, upper, out);
}

// round 2
// speedup vs baseline: 1.1645x; 1.1645x over previous
#include <cuda_runtime.h>

// Problem constants (fixed by setup_inputs)
#define B_ 16
#define T_ 8192
#define D_ 64
#define CHUNK 16          // == WINDOW
#define CPT 4             // chunks per thread -> 64 timesteps per thread
#define TPT (CHUNK * CPT) // 64
#define YDIM 4
#define BLOCK_T (TPT * YDIM) // 256 timesteps per block

__device__ __forceinline__ float fexp2(float x) {
    float y; asm("ex2.approx.ftz.f32 %0, %1;" : "=f"(y) : "f"(x)); return y;
}
__device__ __forceinline__ float flog2(float x) {
    float y; asm("lg2.approx.ftz.f32 %0, %1;" : "=f"(y) : "f"(x)); return y;
}

// out[b,t,d] = -(1/5) * log( sum_{k=0..15} exp(-5 * x[b, max(t-k,0), d]) )
// Chunked prefix/suffix decomposition: window [t-15, t] spans at most two
// 16-aligned chunks; window_sum = prefix_cur[r] + suffix_prev[r+1].
__global__ __launch_bounds__(256) void always_kernel(
    const float* __restrict__ lower,
    const float* __restrict__ upper,
    float* __restrict__ out)
{
    const float C1 = -7.2134752044448169f;   // -5 * log2(e)
    const float C2 = -0.13862943611198906f;  // -ln(2) / 5

    const int d  = threadIdx.x;              // 0..63 (lanes -> consecutive d: coalesced)
    const int b  = blockIdx.y;               // 0..15
    const int tr = blockIdx.z;               // 0: lower, 1: upper
    const int t0 = blockIdx.x * BLOCK_T + threadIdx.y * TPT;

    const float* src = tr ? upper : lower;
    float*       dst = out + (size_t)tr * ((size_t)B_ * T_ * D_);

    const float* col  = src + (size_t)b * T_ * D_ + d;   // index by t*D_
    float*       ocol = dst + (size_t)b * T_ * D_ + d;

    // Build the initial suffix sums from the 15 preceding (index-clamped) values.
    // suf[k] = sum_{j=k..15} exp(-5 * x[t0-16+j])   (k = 1..15)
    // The clamp to index 0 reproduces h0's replication of x[:,0,:] exactly
    // (duplicates ARE counted in the logsumexp, matching the reference).
    float suf[16];
    {
        float ep[16];
        #pragma unroll
        for (int k = 1; k < 16; k++) {
            int t = t0 - 16 + k;
            if (t < 0) t = 0;
            ep[k] = fexp2(col[t * D_] * C1);
        }
        float run = 0.0f;
        #pragma unroll
        for (int k = 15; k >= 1; k--) { run += ep[k]; suf[k] = run; }
    }

    int tc = t0;
    #pragma unroll 1
    for (int c = 0; c < CPT; c++) {
        // 16 independent loads -> high MLP; one coalesced 128B txn per warp each.
        float e[16];
        #pragma unroll
        for (int r = 0; r < 16; r++)
            e[r] = fexp2(col[(tc + r) * D_] * C1);

        // Running prefix + previous-chunk suffix = exact 16-term window sum.
        float pre = 0.0f;
        #pragma unroll
        for (int r = 0; r < 16; r++) {
            pre += e[r];
            float s = (r < 15) ? (pre + suf[r + 1]) : pre;
            ocol[(tc + r) * D_] = flog2(s) * C2;
        }

        // This chunk becomes the "previous chunk" for the next iteration.
        float run = 0.0f;
        #pragma unroll
        for (int k = 15; k >= 1; k--) { run += e[k]; suf[k] = run; }

        tc += CHUNK;
    }
}

extern "C" void kernel_launch(void* const* d_in, const int* in_sizes, int n_in,
                              void* d_out, int out_size) {
    const float* lower = (const float*)d_in[0];
    const float* upper = (const float*)d_in[1];
    float* out = (float*)d_out;

    dim3 block(D_, YDIM);                  // 64 x 4 = 256 threads
    dim3 grid(T_ / BLOCK_T, B_, 2);        // 32 x 16 x 2 = 1024 blocks
    always_kernel<<<grid, block>>>(lower, upper, out);
}

// round 3
// speedup vs baseline: 1.2349x; 1.0604x over previous
#include <cuda_runtime.h>

// Problem constants (fixed by setup_inputs)
#define B_ 16
#define T_ 8192
#define D_ 64
#define D2 (D_ / 2)       // 32 float2 columns
#define CHUNK 16          // == WINDOW
#define CPT 2             // chunks per thread -> 32 timesteps per thread
#define TPT (CHUNK * CPT) // 32
#define YDIM 8
#define BLOCK_T (TPT * YDIM) // 256 timesteps per block

__device__ __forceinline__ float fexp2(float x) {
    float y; asm("ex2.approx.ftz.f32 %0, %1;" : "=f"(y) : "f"(x)); return y;
}
__device__ __forceinline__ float flog2(float x) {
    float y; asm("lg2.approx.ftz.f32 %0, %1;" : "=f"(y) : "f"(x)); return y;
}

// out[b,t,d] = -(1/5) * log( sum_{k=0..15} exp(-5 * x[b, max(t-k,0), d]) )
// Chunked prefix/suffix decomposition; float2-vectorized over D so each
// LSU slot moves 8B/lane (LDG.64/STG.64) instead of 4B — the R2 profile
// showed the LDG->LDG dispatch floor (4cyc) as the binder.
__global__ __launch_bounds__(256) void always_kernel(
    const float* __restrict__ lower,
    const float* __restrict__ upper,
    float* __restrict__ out)
{
    const float C1 = -7.2134752044448169f;   // -5 * log2(e)
    const float C2 = -0.13862943611198906f;  // -ln(2) / 5

    const int d2 = threadIdx.x;              // 0..31 float2 column (coalesced)
    const int b  = blockIdx.y;               // 0..15
    const int tr = blockIdx.z;               // 0: lower, 1: upper
    const int t0 = blockIdx.x * BLOCK_T + threadIdx.y * TPT;

    const float* src = tr ? upper : lower;
    float*       dst = out + (size_t)tr * ((size_t)B_ * T_ * D_);

    const float2* col  = (const float2*)src + (size_t)b * T_ * D2 + d2;
    float2*       ocol = (float2*)dst      + (size_t)b * T_ * D2 + d2;

    // Suffix sums of the 15 preceding (index-clamped) timesteps.
    // Index clamp to 0 reproduces h0's replication of x[:,0,:] exactly
    // (duplicates ARE counted in the logsumexp, matching the reference).
    float sfx[16], sfy[16];
    {
        float ex[16], ey[16];
        #pragma unroll
        for (int k = 1; k < 16; k++) {
            int t = t0 - 16 + k;
            if (t < 0) t = 0;
            float2 v = col[t * D2];
            ex[k] = fexp2(v.x * C1);
            ey[k] = fexp2(v.y * C1);
        }
        float rx = 0.0f, ry = 0.0f;
        #pragma unroll
        for (int k = 15; k >= 1; k--) {
            rx += ex[k]; sfx[k] = rx;
            ry += ey[k]; sfy[k] = ry;
        }
    }

    int tc = t0;
    #pragma unroll 1
    for (int c = 0; c < CPT; c++) {
        // 16 independent LDG.64 -> high MLP, 256B per warp per slot.
        float ex[16], ey[16];
        #pragma unroll
        for (int r = 0; r < 16; r++) {
            float2 v = col[(tc + r) * D2];
            ex[r] = fexp2(v.x * C1);
            ey[r] = fexp2(v.y * C1);
        }

        // window_sum = prefix_cur[r] + suffix_prev[r+1] (exact 16-term sum).
        float px = 0.0f, py = 0.0f;
        #pragma unroll
        for (int r = 0; r < 16; r++) {
            px += ex[r];
            py += ey[r];
            float wx = (r < 15) ? (px + sfx[r + 1]) : px;
            float wy = (r < 15) ? (py + sfy[r + 1]) : py;
            float2 o;
            o.x = flog2(wx) * C2;
            o.y = flog2(wy) * C2;
            ocol[(tc + r) * D2] = o;
        }

        // This chunk's suffix sums become "previous" for the next iteration.
        float rx = 0.0f, ry = 0.0f;
        #pragma unroll
        for (int k = 15; k >= 1; k--) {
            rx += ex[k]; sfx[k] = rx;
            ry += ey[k]; sfy[k] = ry;
        }

        tc += CHUNK;
    }
}

extern "C" void kernel_launch(void* const* d_in, const int* in_sizes, int n_in,
                              void* d_out, int out_size) {
    const float* lower = (const float*)d_in[0];
    const float* upper = (const float*)d_in[1];
    float* out = (float*)d_out;

    dim3 block(D2, YDIM);                  // 32 x 8 = 256 threads
    dim3 grid(T_ / BLOCK_T, B_, 2);        // 32 x 16 x 2 = 1024 blocks
    always_kernel<<<grid, block>>>(lower, upper, out);
}

// round 4
// speedup vs baseline: 1.4876x; 1.2047x over previous
#include <cuda_runtime.h>

// Problem constants (fixed by setup_inputs)
#define B_ 16
#define T_ 8192
#define D_ 64
#define D2 (D_ / 2)       // 32 float2 columns
#define CHUNK 16          // == WINDOW
#define CPT 4             // chunks per thread -> 64 timesteps per thread
#define TPT (CHUNK * CPT) // 64
#define YDIM 4
#define BLOCK_T (TPT * YDIM) // 256 timesteps per block

__device__ __forceinline__ float fexp2(float x) {
    float y; asm("ex2.approx.ftz.f32 %0, %1;" : "=f"(y) : "f"(x)); return y;
}
__device__ __forceinline__ float flog2(float x) {
    float y; asm("lg2.approx.ftz.f32 %0, %1;" : "=f"(y) : "f"(x)); return y;
}

// out[b,t,d] = -(1/5) * log( sum_{k=0..15} exp(-5 * x[b, max(t-k,0), d]) )
// Chunked prefix/suffix decomposition, float2 over D (LDG.64/STG.64).
// 128-thread blocks * 1024 blocks at <=64 regs -> 8 blocks/SM -> the whole
// grid is resident in ONE wave (no wave-quantization tail). CPT=4 cuts the
// per-thread halo from 47% to 23% extra loads/ex2.
__global__ __launch_bounds__(128, 8) void always_kernel(
    const float* __restrict__ lower,
    const float* __restrict__ upper,
    float* __restrict__ out)
{
    const float C1 = -7.2134752044448169f;   // -5 * log2(e)
    const float C2 = -0.13862943611198906f;  // -ln(2) / 5

    const int d2 = threadIdx.x;              // 0..31 float2 column (coalesced)
    const int b  = blockIdx.y;               // 0..15
    const int tr = blockIdx.z;               // 0: lower, 1: upper
    const int t0 = blockIdx.x * BLOCK_T + threadIdx.y * TPT;

    const float* src = tr ? upper : lower;
    float*       dst = out + (size_t)tr * ((size_t)B_ * T_ * D_);

    const float2* col  = (const float2*)src + (size_t)b * T_ * D2 + d2;
    float2*       ocol = (float2*)dst      + (size_t)b * T_ * D2 + d2;

    // Suffix sums of the 15 preceding (index-clamped) timesteps.
    // Index clamp to 0 reproduces h0's replication of x[:,0,:] exactly
    // (duplicates ARE counted in the logsumexp, matching the reference).
    float sfx[16], sfy[16];
    {
        float ex[16], ey[16];
        #pragma unroll
        for (int k = 1; k < 16; k++) {
            int t = t0 - 16 + k;
            if (t < 0) t = 0;
            float2 v = col[t * D2];
            ex[k] = fexp2(v.x * C1);
            ey[k] = fexp2(v.y * C1);
        }
        float rx = 0.0f, ry = 0.0f;
        #pragma unroll
        for (int k = 15; k >= 1; k--) {
            rx += ex[k]; sfx[k] = rx;
            ry += ey[k]; sfy[k] = ry;
        }
    }

    int tc = t0;
    #pragma unroll 1
    for (int c = 0; c < CPT; c++) {
        // 16 independent LDG.64 -> high MLP, 256B per warp per slot.
        float ex[16], ey[16];
        #pragma unroll
        for (int r = 0; r < 16; r++) {
            float2 v = col[(tc + r) * D2];
            ex[r] = fexp2(v.x * C1);
            ey[r] = fexp2(v.y * C1);
        }

        // window_sum = prefix_cur[r] + suffix_prev[r+1] (exact 16-term sum).
        float px = 0.0f, py = 0.0f;
        #pragma unroll
        for (int r = 0; r < 16; r++) {
            px += ex[r];
            py += ey[r];
            float wx = (r < 15) ? (px + sfx[r + 1]) : px;
            float wy = (r < 15) ? (py + sfy[r + 1]) : py;
            float2 o;
            o.x = flog2(wx) * C2;
            o.y = flog2(wy) * C2;
            ocol[(tc + r) * D2] = o;
        }

        // This chunk's suffix sums become "previous" for the next iteration.
        float rx = 0.0f, ry = 0.0f;
        #pragma unroll
        for (int k = 15; k >= 1; k--) {
            rx += ex[k]; sfx[k] = rx;
            ry += ey[k]; sfy[k] = ry;
        }

        tc += CHUNK;
    }
}

extern "C" void kernel_launch(void* const* d_in, const int* in_sizes, int n_in,
                              void* d_out, int out_size) {
    const float* lower = (const float*)d_in[0];
    const float* upper = (const float*)d_in[1];
    float* out = (float*)d_out;

    dim3 block(D2, YDIM);                  // 32 x 4 = 128 threads
    dim3 grid(T_ / BLOCK_T, B_, 2);        // 32 x 16 x 2 = 1024 blocks
    always_kernel<<<grid, block>>>(lower, upper, out);
}